// round 16
// baseline (speedup 1.0000x reference)
#include <cuda_runtime.h>
#include <cuda_fp16.h>
#include <cuda_bf16.h>
#include <math.h>

#define ATOMS_MAX 50000
#define EDGES_MAX 1600000
#define BN_EPS 1e-5f

// ---------------- scratch (device globals) ----------------
__device__ __align__(16) float g_Pself[ATOMS_MAX * 128];            // 25.6 MB (bias folded in)
__device__ __align__(16) float g_Pnbr [ATOMS_MAX * 128];            // 25.6 MB
__device__ __align__(16) __half g_yh[(size_t)EDGES_MAX * 128];      // 410 MB
__device__ __align__(16) float g_ns[ATOMS_MAX * 64];                // 12.8 MB
__device__ int   g_start[ATOMS_MAX + 1];
__device__ float g_bn1s[128], g_bn1q[128];
__device__ float g_bn2s[64],  g_bn2q[64];

__device__ __forceinline__ float sigmoid_f(float x) {
    return __fdividef(1.0f, 1.0f + __expf(-x));
}
__device__ __forceinline__ float softplus_f(float x) {
    return fmaxf(x, 0.0f) + __logf(1.0f + __expf(-fabsf(x)));
}

// ---------------- helpers ----------------
__device__ __forceinline__ unsigned smem_u32(const void* p) {
    unsigned a;
    asm("{ .reg .u64 t; cvta.to.shared.u64 t, %1; cvt.u32.u64 %0, t; }" : "=r"(a) : "l"(p));
    return a;
}
__device__ __forceinline__ void ldm_x4(unsigned* r, unsigned addr) {
    asm volatile("ldmatrix.sync.aligned.m8n8.x4.shared.b16 {%0,%1,%2,%3}, [%4];"
                 : "=r"(r[0]), "=r"(r[1]), "=r"(r[2]), "=r"(r[3]) : "r"(addr));
}
__device__ __forceinline__ void mma16816(float* c, const unsigned* a, unsigned b0, unsigned b1) {
    asm volatile(
        "mma.sync.aligned.m16n8k16.row.col.f32.bf16.bf16.f32 "
        "{%0,%1,%2,%3}, {%4,%5,%6,%7}, {%8,%9}, {%0,%1,%2,%3};"
        : "+f"(c[0]), "+f"(c[1]), "+f"(c[2]), "+f"(c[3])
        : "r"(a[0]), "r"(a[1]), "r"(a[2]), "r"(a[3]), "r"(b0), "r"(b1));
}
__device__ __forceinline__ unsigned pack_bf16x2(float a, float b) {
    unsigned short ha = __bfloat16_as_ushort(__float2bfloat16(a));
    unsigned short hb = __bfloat16_as_ushort(__float2bfloat16(b));
    return (unsigned)ha | ((unsigned)hb << 16);
}
__device__ __forceinline__ void bf16split(float v, unsigned short& h, unsigned short& l) {
    __nv_bfloat16 hb = __float2bfloat16(v);
    __nv_bfloat16 lb = __float2bfloat16(v - __bfloat162float(hb));
    h = __bfloat16_as_ushort(hb);
    l = __bfloat16_as_ushort(lb);
}

// ---------------- k_init ----------------
__global__ void k_init(int N, int E) {
    int i = blockIdx.x * blockDim.x + threadIdx.x;
    if (i < 128) { g_bn1s[i] = 0.f; g_bn1q[i] = 0.f; }
    if (i < 64)  { g_bn2s[i] = 0.f; g_bn2q[i] = 0.f; }
    if (i <= N)  g_start[i] = E;
}

// ---------------- k_proj_mma: P = atom @ Wp via exact bf16-split HMMA ----------
// A split: row = [a_hi(64) | a_lo(64)] bf16, K_eff=128. B split likewise.
// pass1 Σ_j A_j·B_j = hi·hi + lo·lo ; pass2 Σ_j A_{j^4}·B_j = hi·lo + lo·hi.
// smem: sA 64 x 136 ush (272B stride), sB 128 x 136 ush
#define PSTRIDE 136
#define POFF_A  0
#define POFF_B  (64 * PSTRIDE * 2)             // 17408
#define PSMEM   (POFF_B + 128 * PSTRIDE * 2)   // 52224

__global__ __launch_bounds__(256, 2) void k_proj_mma(const float* __restrict__ atom,
                                                     const float* __restrict__ W,
                                                     const float* __restrict__ bias,
                                                     int N) {
    extern __shared__ char sm[];
    unsigned short* sA = (unsigned short*)(sm + POFF_A);
    unsigned short* sB = (unsigned short*)(sm + POFF_B);

    int which = blockIdx.y;
    float* __restrict__ P = which ? g_Pnbr : g_Pself;

    int tid = threadIdx.x;
    int wid = tid >> 5;
    int lane = tid & 31;
    int a0 = blockIdx.x * 64;

    // build B: n=0..127, k=0..63 ; w = W[(which*64+k)*128 + n]
    for (int i = tid; i < 128 * 64; i += 256) {
        int n = i >> 6, k = i & 63;
        float w = W[(which * 64 + k) * 128 + n];
        unsigned short hi, lo;
        bf16split(w, hi, lo);
        sB[n * PSTRIDE + k]      = hi;
        sB[n * PSTRIDE + 64 + k] = lo;
    }

    // load A tile: 64 atoms x 64 fp32 -> [hi|lo] bf16
    {
        int row = tid >> 2, part = tid & 3;    // 16 cols per thread
        int a = a0 + row;
        bool v = a < N;
        const float4* src = (const float4*)(atom + (size_t)a * 64 + part * 16);
        unsigned short* dst = sA + row * PSTRIDE + part * 16;
#pragma unroll
        for (int j = 0; j < 4; j++) {
            float4 x = v ? src[j] : make_float4(0.f, 0.f, 0.f, 0.f);
            unsigned short h0, l0, h1, l1, h2, l2, h3, l3;
            bf16split(x.x, h0, l0); bf16split(x.y, h1, l1);
            bf16split(x.z, h2, l2); bf16split(x.w, h3, l3);
            uint2 hp, lp;
            hp.x = (unsigned)h0 | ((unsigned)h1 << 16);
            hp.y = (unsigned)h2 | ((unsigned)h3 << 16);
            lp.x = (unsigned)l0 | ((unsigned)l1 << 16);
            lp.y = (unsigned)l2 | ((unsigned)l3 << 16);
            *(uint2*)(dst + j * 4)      = hp;
            *(uint2*)(dst + 64 + j * 4) = lp;
        }
    }
    __syncthreads();

    int g = wid >> 1;      // m-group: rows g*16..g*16+15
    int h = wid & 1;       // n-half: cols h*64..h*64+63

    unsigned aBase = smem_u32(sA);
    unsigned bBase = smem_u32(sB);

    int arow = g * 16 + (lane & 7) + ((lane >> 3) & 1) * 8;
    int acol8 = (lane >> 4);
    unsigned bRowOff4 = (unsigned)((h * 64 + ((lane >> 4) & 1) * 8 + (lane & 7)) * (PSTRIDE * 2)
                                   + ((lane >> 3) & 1) * 16);

    float acc[8][4];
#pragma unroll
    for (int nt = 0; nt < 8; nt++)
#pragma unroll
        for (int r = 0; r < 4; r++) acc[nt][r] = 0.f;

    unsigned af[8][4];
    {
        unsigned base = aBase + (unsigned)(arow * (PSTRIDE * 2));
#pragma unroll
        for (int j = 0; j < 8; j++)
            ldm_x4(af[j], base + (unsigned)((j * 16 + 8 * acol8) * 2));
    }
#pragma unroll
    for (int j = 0; j < 8; j++) {
#pragma unroll
        for (int p = 0; p < 4; p++) {
            unsigned bf[4];
            ldm_x4(bf, bBase + bRowOff4 + (unsigned)(j * 32 + p * 16 * (PSTRIDE * 2)));
            mma16816(acc[2 * p],     af[j],     bf[0], bf[1]);
            mma16816(acc[2 * p + 1], af[j],     bf[2], bf[3]);
            mma16816(acc[2 * p],     af[j ^ 4], bf[0], bf[1]);
            mma16816(acc[2 * p + 1], af[j ^ 4], bf[2], bf[3]);
        }
    }

    // epilogue: direct fragment store + bias (which==0 only)
    {
        int rq = lane >> 2, cq = lane & 3;
        int r_lo = a0 + g * 16 + rq;
        int r_hi = r_lo + 8;
#pragma unroll
        for (int nt = 0; nt < 8; nt++) {
            int c = h * 64 + nt * 8 + 2 * cq;
            float2 bb = make_float2(0.f, 0.f);
            if (which == 0) bb = *(const float2*)&bias[c];
            if (r_lo < N)
                *(float2*)&P[(size_t)r_lo * 128 + c] =
                    make_float2(acc[nt][0] + bb.x, acc[nt][1] + bb.y);
            if (r_hi < N)
                *(float2*)&P[(size_t)r_hi * 128 + c] =
                    make_float2(acc[nt][2] + bb.x, acc[nt][3] + bb.y);
        }
    }
}

// ---------------- k_edge_mma v12: K=32 single-bf16, 4 CTAs/SM ----------------
// smem: [0..256) sidx, [256..512) nidx,
// [512..5632)   sA (64 x 40 bf16, 80B stride)
// [5632..15872) sB (128 x 40 bf16, 80B)
// [16384..50176) sY (64 x 132 fp32, 528B)
#define EOFF_S   0
#define EOFF_N   256
#define EOFF_A   512
#define EOFF_B   5632
#define EOFF_Y   16384
#define ESMEM    (16384 + 64 * 132 * 4)    // 50176
#define ASTRIDE  40     // ushorts per row (80 bytes)
#define YSTRIDE  132    // floats per row (528 bytes)

__global__ __launch_bounds__(256, 4) void k_edge_mma(const float* __restrict__ nbr,
                                                     const int* __restrict__ sidx,
                                                     const int* __restrict__ nidx,
                                                     const float* __restrict__ W,
                                                     int E, int ET) {
    extern __shared__ char sm[];
    int*   sS = (int*)(sm + EOFF_S);
    int*   sN = (int*)(sm + EOFF_N);
    unsigned short* sA = (unsigned short*)(sm + EOFF_A);
    unsigned short* sB = (unsigned short*)(sm + EOFF_B);
    float* sY = (float*)(sm + EOFF_Y);

    int tid = threadIdx.x;
    int wid = tid >> 5;
    int lane = tid & 31;

    // build B: single bf16 of W rows 128..159, per output row n
    for (int i = tid; i < 128 * 32; i += 256) {
        int n = i >> 5, k = i & 31;
        sB[n * ASTRIDE + k] = __bfloat16_as_ushort(__float2bfloat16(W[(128 + k) * 128 + n]));
    }

    int g = wid >> 1;      // m-group: rows g*16..g*16+15
    int h = wid & 1;       // n-half: cols h*64..h*64+63

    unsigned aBase = smem_u32(sA);
    unsigned bBase = smem_u32(sB);

    int arow = g * 16 + (lane & 7) + ((lane >> 3) & 1) * 8;
    int acol8 = (lane >> 4);
    unsigned bRowOff4 = (unsigned)((h * 64 + ((lane >> 4) & 1) * 8 + (lane & 7)) * 80
                                   + ((lane >> 3) & 1) * 16);

    // BN1 stat accumulators (cols lane*4..lane*4+3)
    float4 st = make_float4(0.f, 0.f, 0.f, 0.f);
    float4 sq = make_float4(0.f, 0.f, 0.f, 0.f);

    // Pself run-length cache (persistent across tiles; sidx sorted)
    int sPrev = -1;
    float4 ps = make_float4(0.f, 0.f, 0.f, 0.f);

    for (int tile = blockIdx.x; tile < ET; tile += gridDim.x) {
        int e0 = tile * 64;
        __syncthreads();   // smem reuse vs previous epilogue / B build

        // ---- A tile: 64 edges x 32 fp32 -> bf16 (one uint4 STS per thread) ----
        {
            int row = tid >> 2, part = tid & 3;   // 8 cols per thread
            int e = e0 + row;
            bool v = e < E;
            const float4* src = (const float4*)(nbr + (size_t)e * 32 + part * 8);
            float4 x0 = v ? src[0] : make_float4(0.f, 0.f, 0.f, 0.f);
            float4 x1 = v ? src[1] : make_float4(0.f, 0.f, 0.f, 0.f);
            uint4 u;
            u.x = pack_bf16x2(x0.x, x0.y);
            u.y = pack_bf16x2(x0.z, x0.w);
            u.z = pack_bf16x2(x1.x, x1.y);
            u.w = pack_bf16x2(x1.z, x1.w);
            *(uint4*)(sA + row * ASTRIDE + part * 8) = u;
            if (tid < 64) {
                int e2 = e0 + tid;
                if (e2 < E) {
                    int cur = sidx[e2];
                    sS[tid] = cur;
                    sN[tid] = nidx[e2];
                    int prev = (e2 == 0) ? -1 : sidx[e2 - 1];
                    for (int a = prev + 1; a <= cur; a++) g_start[a] = e2;
                } else {
                    sS[tid] = 0;
                    sN[tid] = 0;
                }
            }
        }
        __syncthreads();

        // ---- MMA: K=32, 2 k-steps, single bf16 ----
        float acc[8][4];
#pragma unroll
        for (int nt = 0; nt < 8; nt++)
#pragma unroll
            for (int r = 0; r < 4; r++) acc[nt][r] = 0.f;

        unsigned af[2][4];
        {
            unsigned base = aBase + (unsigned)(arow * 80);
#pragma unroll
            for (int j = 0; j < 2; j++)
                ldm_x4(af[j], base + (unsigned)((j * 16 + 8 * acol8) * 2));
        }
#pragma unroll
        for (int j = 0; j < 2; j++) {
#pragma unroll
            for (int p = 0; p < 4; p++) {          // nt pairs: (2p, 2p+1)
                unsigned bf[4];
                ldm_x4(bf, bBase + bRowOff4 + (unsigned)(j * 32 + p * 16 * 80));
                mma16816(acc[2 * p],     af[j], bf[0], bf[1]);
                mma16816(acc[2 * p + 1], af[j], bf[2], bf[3]);
            }
        }

        // ---- stage acc -> sY (all 64 rows) ----
        {
            int rq = lane >> 2, cq = lane & 3;
            int r0 = g * 16 + rq;
#pragma unroll
            for (int nt = 0; nt < 8; nt++) {
                int c = h * 64 + nt * 8 + 2 * cq;
                *(float2*)&sY[r0 * YSTRIDE + c]       = make_float2(acc[nt][0], acc[nt][1]);
                *(float2*)&sY[(r0 + 8) * YSTRIDE + c] = make_float2(acc[nt][2], acc[nt][3]);
            }
        }
        __syncthreads();

        // ---- single epilogue: warp w -> rows w*8..w*8+7; Pself run cached ----
#pragma unroll 2
        for (int i = 0; i < 8; i++) {
            int row = wid * 8 + i;
            int e = e0 + row;
            if (e >= E) continue;
            int s = sS[row], n = sN[row];
            if (s != sPrev) {
                ps = ((const float4*)(g_Pself + (size_t)s * 128))[lane];
                sPrev = s;
            }
            float4 a4 = *(const float4*)&sY[row * YSTRIDE + lane * 4];
            float4 pn = ((const float4*)(g_Pnbr + (size_t)n * 128))[lane];
            float y0 = a4.x + ps.x + pn.x;
            float y1 = a4.y + ps.y + pn.y;
            float y2 = a4.z + ps.z + pn.z;
            float y3 = a4.w + ps.w + pn.w;
            st.x += y0; st.y += y1; st.z += y2; st.w += y3;
            sq.x += y0 * y0; sq.y += y1 * y1; sq.z += y2 * y2; sq.w += y3 * y3;
            __half2 p01 = __floats2half2_rn(y0, y1);
            __half2 p23 = __floats2half2_rn(y2, y3);
            uint2 u;
            u.x = *(unsigned*)&p01;
            u.y = *(unsigned*)&p23;
            __stcs((uint2*)(g_yh + (size_t)e * 128 + lane * 4), u);
        }
    }

    // ---- BN1 stats: cross-warp reduce in smem, one atomicAdd per col per CTA ----
    __syncthreads();
    *(float4*)&sY[wid * 128 + lane * 4] = st;
    *(float4*)&sY[1024 + wid * 128 + lane * 4] = sq;
    __syncthreads();
    if (tid < 128) {
        float a = 0.f, b = 0.f;
#pragma unroll
        for (int w = 0; w < 8; w++) {
            a += sY[w * 128 + tid];
            b += sY[1024 + w * 128 + tid];
        }
        atomicAdd(&g_bn1s[tid], a);
        atomicAdd(&g_bn1q[tid], b);
    }
}

// ---------------- k_atom: BN1 fold + message + segment sum + BN2 stats ----------
__global__ __launch_bounds__(256) void k_atom(const float* __restrict__ gamma1,
                                              const float* __restrict__ beta1,
                                              int N, int E) {
    __shared__ float sv[8 * 64], sv2[8 * 64];
    int wid = threadIdx.x >> 5;
    int lane = threadIdx.x & 31;
    int a = blockIdx.x * 8 + wid;
    bool active = a < N;

    // fold BN1 per warp
    float inv_n = 1.0f / (float)E;
    float2 a1f, c1f, a1c, c1c;
    {
        float2 s1 = ((const float2*)g_bn1s)[lane];
        float2 q1 = ((const float2*)g_bn1q)[lane];
        float2 gg = ((const float2*)gamma1)[lane];
        float2 bb = ((const float2*)beta1)[lane];
        float m0 = s1.x * inv_n, m1 = s1.y * inv_n;
        a1f.x = gg.x * rsqrtf(q1.x * inv_n - m0 * m0 + BN_EPS);
        a1f.y = gg.y * rsqrtf(q1.y * inv_n - m1 * m1 + BN_EPS);
        c1f.x = bb.x - a1f.x * m0;
        c1f.y = bb.y - a1f.y * m1;
        float2 s2 = ((const float2*)g_bn1s)[32 + lane];
        float2 q2 = ((const float2*)g_bn1q)[32 + lane];
        float2 g2 = ((const float2*)gamma1)[32 + lane];
        float2 b2 = ((const float2*)beta1)[32 + lane];
        float m2 = s2.x * inv_n, m3 = s2.y * inv_n;
        a1c.x = g2.x * rsqrtf(q2.x * inv_n - m2 * m2 + BN_EPS);
        a1c.y = g2.y * rsqrtf(q2.y * inv_n - m3 * m3 + BN_EPS);
        c1c.x = b2.x - a1c.x * m2;
        c1c.y = b2.y - a1c.y * m3;
    }

    float sx = 0.f, sy = 0.f;
    if (active) {
        int eb = g_start[a], ee = g_start[a + 1];
        int e = eb;
        for (; e + 4 <= ee; e += 4) {
            float2 F[4], G[4];
#pragma unroll
            for (int q = 0; q < 4; q++) {
                const __half2* y = (const __half2*)(g_yh + (size_t)(e + q) * 128);
                F[q] = __half22float2(__ldcs(&y[lane]));
                G[q] = __half22float2(__ldcs(&y[32 + lane]));
            }
#pragma unroll
            for (int q = 0; q < 4; q++) {
                sx += sigmoid_f(fmaf(a1f.x, F[q].x, c1f.x)) * softplus_f(fmaf(a1c.x, G[q].x, c1c.x));
                sy += sigmoid_f(fmaf(a1f.y, F[q].y, c1f.y)) * softplus_f(fmaf(a1c.y, G[q].y, c1c.y));
            }
        }
        for (; e < ee; e++) {
            const __half2* y = (const __half2*)(g_yh + (size_t)e * 128);
            float2 F0 = __half22float2(__ldcs(&y[lane]));
            float2 G0 = __half22float2(__ldcs(&y[32 + lane]));
            sx += sigmoid_f(fmaf(a1f.x, F0.x, c1f.x)) * softplus_f(fmaf(a1c.x, G0.x, c1c.x));
            sy += sigmoid_f(fmaf(a1f.y, F0.y, c1f.y)) * softplus_f(fmaf(a1c.y, G0.y, c1c.y));
        }
        ((float2*)g_ns)[(size_t)a * 32 + lane] = make_float2(sx, sy);
    }

    // BN2 stats: block reduce over 8 atoms, 128 atomics per block
    ((float2*)sv)[wid * 32 + lane]  = make_float2(sx, sy);
    ((float2*)sv2)[wid * 32 + lane] = make_float2(sx * sx, sy * sy);
    __syncthreads();
    if (threadIdx.x < 64) {
        int f = threadIdx.x;
        float s = 0.f, q = 0.f;
#pragma unroll
        for (int w = 0; w < 8; w++) {
            s += sv[w * 64 + f];
            q += sv2[w * 64 + f];
        }
        atomicAdd(&g_bn2s[f], s);
        atomicAdd(&g_bn2q[f], q);
    }
}

// ---------------- fused final ----------------
__global__ void k_final(const float* __restrict__ atom,
                        const float* __restrict__ gamma2,
                        const float* __restrict__ beta2,
                        float* __restrict__ out, int N) {
    int i = blockIdx.x * blockDim.x + threadIdx.x;
    if (i >= N * 64) return;
    int f = i & 63;
    float inv_n = 1.0f / (float)N;
    float mean = g_bn2s[f] * inv_n;
    float var  = g_bn2q[f] * inv_n - mean * mean;
    float a2 = gamma2[f] * rsqrtf(var + BN_EPS);
    float c2 = beta2[f] - a2 * mean;
    float v = atom[i] + a2 * g_ns[i] + c2;
    out[i] = softplus_f(v);
}

// ---------------- launch ----------------
extern "C" void kernel_launch(void* const* d_in, const int* in_sizes, int n_in,
                              void* d_out, int out_size) {
    const float* atom   = (const float*)d_in[0];
    const float* nbr    = (const float*)d_in[1];
    const int*   sidx   = (const int*)d_in[2];
    const int*   nidx   = (const int*)d_in[3];
    const float* W      = (const float*)d_in[4];
    const float* bias   = (const float*)d_in[5];
    const float* gamma1 = (const float*)d_in[6];
    const float* beta1  = (const float*)d_in[7];
    const float* gamma2 = (const float*)d_in[8];
    const float* beta2  = (const float*)d_in[9];
    float* out = (float*)d_out;

    int N = in_sizes[0] / 64;
    int E = in_sizes[2];
    int ET = (E + 63) / 64;

    cudaFuncSetAttribute(k_edge_mma, cudaFuncAttributeMaxDynamicSharedMemorySize, ESMEM);
    cudaFuncSetAttribute(k_proj_mma, cudaFuncAttributeMaxDynamicSharedMemorySize, PSMEM);

    k_init<<<(N + 256) / 256, 256>>>(N, E);
    {
        dim3 grid((N + 63) / 64, 2);
        k_proj_mma<<<grid, 256, PSMEM>>>(atom, W, bias, N);
    }
    k_edge_mma<<<592, 256, ESMEM>>>(nbr, sidx, nidx, W, E, ET);
    k_atom<<<(N + 7) / 8, 256>>>(gamma1, beta1, N, E);
    k_final<<<(N * 64 + 255) / 256, 256>>>(atom, gamma2, beta2, out, N);
}

// round 17
// speedup vs baseline: 1.1921x; 1.1921x over previous
#include <cuda_runtime.h>
#include <cuda_fp16.h>
#include <cuda_bf16.h>
#include <math.h>

#define ATOMS_MAX 50000
#define EDGES_MAX 1600000
#define BN_EPS 1e-5f

// ---------------- scratch (device globals) ----------------
__device__ __align__(16) float g_Pself[ATOMS_MAX * 128];            // 25.6 MB (bias folded in)
__device__ __align__(16) float g_Pnbr [ATOMS_MAX * 128];            // 25.6 MB
__device__ __align__(16) __half g_yh[(size_t)EDGES_MAX * 128];      // 410 MB
__device__ __align__(16) float g_ns[ATOMS_MAX * 64];                // 12.8 MB
__device__ int   g_start[ATOMS_MAX + 1];
__device__ float g_bn1s[128], g_bn1q[128];
__device__ float g_bn2s[64],  g_bn2q[64];

__device__ __forceinline__ float sigmoid_f(float x) {
    return __fdividef(1.0f, 1.0f + __expf(-x));
}
__device__ __forceinline__ float softplus_f(float x) {
    return fmaxf(x, 0.0f) + __logf(1.0f + __expf(-fabsf(x)));
}

// ---------------- helpers ----------------
__device__ __forceinline__ unsigned smem_u32(const void* p) {
    unsigned a;
    asm("{ .reg .u64 t; cvta.to.shared.u64 t, %1; cvt.u32.u64 %0, t; }" : "=r"(a) : "l"(p));
    return a;
}
__device__ __forceinline__ void ldm_x4(unsigned* r, unsigned addr) {
    asm volatile("ldmatrix.sync.aligned.m8n8.x4.shared.b16 {%0,%1,%2,%3}, [%4];"
                 : "=r"(r[0]), "=r"(r[1]), "=r"(r[2]), "=r"(r[3]) : "r"(addr));
}
__device__ __forceinline__ void mma16816(float* c, const unsigned* a, unsigned b0, unsigned b1) {
    asm volatile(
        "mma.sync.aligned.m16n8k16.row.col.f32.bf16.bf16.f32 "
        "{%0,%1,%2,%3}, {%4,%5,%6,%7}, {%8,%9}, {%0,%1,%2,%3};"
        : "+f"(c[0]), "+f"(c[1]), "+f"(c[2]), "+f"(c[3])
        : "r"(a[0]), "r"(a[1]), "r"(a[2]), "r"(a[3]), "r"(b0), "r"(b1));
}
__device__ __forceinline__ unsigned pack_bf16x2(float a, float b) {
    unsigned short ha = __bfloat16_as_ushort(__float2bfloat16(a));
    unsigned short hb = __bfloat16_as_ushort(__float2bfloat16(b));
    return (unsigned)ha | ((unsigned)hb << 16);
}
__device__ __forceinline__ void bf16split(float v, unsigned short& h, unsigned short& l) {
    __nv_bfloat16 hb = __float2bfloat16(v);
    __nv_bfloat16 lb = __float2bfloat16(v - __bfloat162float(hb));
    h = __bfloat16_as_ushort(hb);
    l = __bfloat16_as_ushort(lb);
}

// ---------------- k_init ----------------
__global__ void k_init(int N, int E) {
    int i = blockIdx.x * blockDim.x + threadIdx.x;
    if (i < 128) { g_bn1s[i] = 0.f; g_bn1q[i] = 0.f; }
    if (i < 64)  { g_bn2s[i] = 0.f; g_bn2q[i] = 0.f; }
    if (i <= N)  g_start[i] = E;
}

// ---------------- k_proj_mma v2: persistent, coalesced B build ----------------
// A split row = [a_hi(64) | a_lo(64)] bf16 (K_eff=128); B likewise.
// pass1 Σ_j A_j·B_j = hi·hi + lo·lo ; pass2 Σ_j A_{j^4}·B_j = hi·lo + lo·hi (exact).
// smem: sA 64 x 136 ush (272B stride), sB 128 x 136 ush
#define PSTRIDE 136
#define POFF_A  0
#define POFF_B  (64 * PSTRIDE * 2)             // 17408
#define PSMEM   (POFF_B + 128 * PSTRIDE * 2)   // 52224

__global__ __launch_bounds__(256, 2) void k_proj_mma(const float* __restrict__ atom,
                                                     const float* __restrict__ W,
                                                     const float* __restrict__ bias,
                                                     int N, int MT) {
    extern __shared__ char sm[];
    unsigned short* sA = (unsigned short*)(sm + POFF_A);
    unsigned short* sB = (unsigned short*)(sm + POFF_B);

    int which = blockIdx.y;
    float* __restrict__ P = which ? g_Pnbr : g_Pself;

    int tid = threadIdx.x;
    int wid = tid >> 5;
    int lane = tid & 31;

    // build B ONCE per CTA, coalesced: n fastest
    for (int i = tid; i < 128 * 64; i += 256) {
        int n = i & 127, k = i >> 7;
        float w = W[(which * 64 + k) * 128 + n];
        unsigned short hi, lo;
        bf16split(w, hi, lo);
        sB[n * PSTRIDE + k]      = hi;
        sB[n * PSTRIDE + 64 + k] = lo;
    }

    int g = wid >> 1;      // m-group: rows g*16..g*16+15
    int h = wid & 1;       // n-half: cols h*64..h*64+63

    unsigned aBase = smem_u32(sA);
    unsigned bBase = smem_u32(sB);

    int arow = g * 16 + (lane & 7) + ((lane >> 3) & 1) * 8;
    int acol8 = (lane >> 4);
    unsigned bRowOff4 = (unsigned)((h * 64 + ((lane >> 4) & 1) * 8 + (lane & 7)) * (PSTRIDE * 2)
                                   + ((lane >> 3) & 1) * 16);

    for (int tile = blockIdx.x; tile < MT; tile += gridDim.x) {
        int a0 = tile * 64;
        __syncthreads();   // sA reuse vs previous MMA / first-iter B build

        // load A tile: 64 atoms x 64 fp32 -> [hi|lo] bf16
        {
            int row = tid >> 2, part = tid & 3;    // 16 cols per thread
            int a = a0 + row;
            bool v = a < N;
            const float4* src = (const float4*)(atom + (size_t)a * 64 + part * 16);
            unsigned short* dst = sA + row * PSTRIDE + part * 16;
#pragma unroll
            for (int j = 0; j < 4; j++) {
                float4 x = v ? src[j] : make_float4(0.f, 0.f, 0.f, 0.f);
                unsigned short h0, l0, h1, l1, h2, l2, h3, l3;
                bf16split(x.x, h0, l0); bf16split(x.y, h1, l1);
                bf16split(x.z, h2, l2); bf16split(x.w, h3, l3);
                uint2 hp, lp;
                hp.x = (unsigned)h0 | ((unsigned)h1 << 16);
                hp.y = (unsigned)h2 | ((unsigned)h3 << 16);
                lp.x = (unsigned)l0 | ((unsigned)l1 << 16);
                lp.y = (unsigned)l2 | ((unsigned)l3 << 16);
                *(uint2*)(dst + j * 4)      = hp;
                *(uint2*)(dst + 64 + j * 4) = lp;
            }
        }
        __syncthreads();

        float acc[8][4];
#pragma unroll
        for (int nt = 0; nt < 8; nt++)
#pragma unroll
            for (int r = 0; r < 4; r++) acc[nt][r] = 0.f;

        unsigned af[8][4];
        {
            unsigned base = aBase + (unsigned)(arow * (PSTRIDE * 2));
#pragma unroll
            for (int j = 0; j < 8; j++)
                ldm_x4(af[j], base + (unsigned)((j * 16 + 8 * acol8) * 2));
        }
#pragma unroll
        for (int j = 0; j < 8; j++) {
#pragma unroll
            for (int p = 0; p < 4; p++) {
                unsigned bf[4];
                ldm_x4(bf, bBase + bRowOff4 + (unsigned)(j * 32 + p * 16 * (PSTRIDE * 2)));
                mma16816(acc[2 * p],     af[j],     bf[0], bf[1]);
                mma16816(acc[2 * p + 1], af[j],     bf[2], bf[3]);
                mma16816(acc[2 * p],     af[j ^ 4], bf[0], bf[1]);
                mma16816(acc[2 * p + 1], af[j ^ 4], bf[2], bf[3]);
            }
        }

        // epilogue: direct fragment store + bias (which==0 only)
        {
            int rq = lane >> 2, cq = lane & 3;
            int r_lo = a0 + g * 16 + rq;
            int r_hi = r_lo + 8;
#pragma unroll
            for (int nt = 0; nt < 8; nt++) {
                int c = h * 64 + nt * 8 + 2 * cq;
                float2 bb = make_float2(0.f, 0.f);
                if (which == 0) bb = *(const float2*)&bias[c];
                if (r_lo < N)
                    *(float2*)&P[(size_t)r_lo * 128 + c] =
                        make_float2(acc[nt][0] + bb.x, acc[nt][1] + bb.y);
                if (r_hi < N)
                    *(float2*)&P[(size_t)r_hi * 128 + c] =
                        make_float2(acc[nt][2] + bb.x, acc[nt][3] + bb.y);
            }
        }
    }
}

// ---------------- k_edge_mma v12: K=32 single-bf16, 4 CTAs/SM ----------------
// smem: [0..256) sidx, [256..512) nidx,
// [512..5632)   sA (64 x 40 bf16, 80B stride)
// [5632..15872) sB (128 x 40 bf16, 80B)
// [16384..50176) sY (64 x 132 fp32, 528B)
#define EOFF_S   0
#define EOFF_N   256
#define EOFF_A   512
#define EOFF_B   5632
#define EOFF_Y   16384
#define ESMEM    (16384 + 64 * 132 * 4)    // 50176
#define ASTRIDE  40     // ushorts per row (80 bytes)
#define YSTRIDE  132    // floats per row (528 bytes)

__global__ __launch_bounds__(256, 4) void k_edge_mma(const float* __restrict__ nbr,
                                                     const int* __restrict__ sidx,
                                                     const int* __restrict__ nidx,
                                                     const float* __restrict__ W,
                                                     int E, int ET) {
    extern __shared__ char sm[];
    int*   sS = (int*)(sm + EOFF_S);
    int*   sN = (int*)(sm + EOFF_N);
    unsigned short* sA = (unsigned short*)(sm + EOFF_A);
    unsigned short* sB = (unsigned short*)(sm + EOFF_B);
    float* sY = (float*)(sm + EOFF_Y);

    int tid = threadIdx.x;
    int wid = tid >> 5;
    int lane = tid & 31;

    // build B: single bf16 of W rows 128..159, per output row n
    for (int i = tid; i < 128 * 32; i += 256) {
        int n = i >> 5, k = i & 31;
        sB[n * ASTRIDE + k] = __bfloat16_as_ushort(__float2bfloat16(W[(128 + k) * 128 + n]));
    }

    int g = wid >> 1;      // m-group: rows g*16..g*16+15
    int h = wid & 1;       // n-half: cols h*64..h*64+63

    unsigned aBase = smem_u32(sA);
    unsigned bBase = smem_u32(sB);

    int arow = g * 16 + (lane & 7) + ((lane >> 3) & 1) * 8;
    int acol8 = (lane >> 4);
    unsigned bRowOff4 = (unsigned)((h * 64 + ((lane >> 4) & 1) * 8 + (lane & 7)) * 80
                                   + ((lane >> 3) & 1) * 16);

    // BN1 stat accumulators (cols lane*4..lane*4+3)
    float4 st = make_float4(0.f, 0.f, 0.f, 0.f);
    float4 sq = make_float4(0.f, 0.f, 0.f, 0.f);

    // Pself run-length cache (persistent across tiles; sidx sorted)
    int sPrev = -1;
    float4 ps = make_float4(0.f, 0.f, 0.f, 0.f);

    for (int tile = blockIdx.x; tile < ET; tile += gridDim.x) {
        int e0 = tile * 64;
        __syncthreads();   // smem reuse vs previous epilogue / B build

        // ---- A tile: 64 edges x 32 fp32 -> bf16 (one uint4 STS per thread) ----
        {
            int row = tid >> 2, part = tid & 3;   // 8 cols per thread
            int e = e0 + row;
            bool v = e < E;
            const float4* src = (const float4*)(nbr + (size_t)e * 32 + part * 8);
            float4 x0 = v ? src[0] : make_float4(0.f, 0.f, 0.f, 0.f);
            float4 x1 = v ? src[1] : make_float4(0.f, 0.f, 0.f, 0.f);
            uint4 u;
            u.x = pack_bf16x2(x0.x, x0.y);
            u.y = pack_bf16x2(x0.z, x0.w);
            u.z = pack_bf16x2(x1.x, x1.y);
            u.w = pack_bf16x2(x1.z, x1.w);
            *(uint4*)(sA + row * ASTRIDE + part * 8) = u;
            if (tid < 64) {
                int e2 = e0 + tid;
                if (e2 < E) {
                    int cur = sidx[e2];
                    sS[tid] = cur;
                    sN[tid] = nidx[e2];
                    int prev = (e2 == 0) ? -1 : sidx[e2 - 1];
                    for (int a = prev + 1; a <= cur; a++) g_start[a] = e2;
                } else {
                    sS[tid] = 0;
                    sN[tid] = 0;
                }
            }
        }
        __syncthreads();

        // ---- MMA: K=32, 2 k-steps, single bf16 ----
        float acc[8][4];
#pragma unroll
        for (int nt = 0; nt < 8; nt++)
#pragma unroll
            for (int r = 0; r < 4; r++) acc[nt][r] = 0.f;

        unsigned af[2][4];
        {
            unsigned base = aBase + (unsigned)(arow * 80);
#pragma unroll
            for (int j = 0; j < 2; j++)
                ldm_x4(af[j], base + (unsigned)((j * 16 + 8 * acol8) * 2));
        }
#pragma unroll
        for (int j = 0; j < 2; j++) {
#pragma unroll
            for (int p = 0; p < 4; p++) {          // nt pairs: (2p, 2p+1)
                unsigned bf[4];
                ldm_x4(bf, bBase + bRowOff4 + (unsigned)(j * 32 + p * 16 * 80));
                mma16816(acc[2 * p],     af[j], bf[0], bf[1]);
                mma16816(acc[2 * p + 1], af[j], bf[2], bf[3]);
            }
        }

        // ---- stage acc -> sY (all 64 rows) ----
        {
            int rq = lane >> 2, cq = lane & 3;
            int r0 = g * 16 + rq;
#pragma unroll
            for (int nt = 0; nt < 8; nt++) {
                int c = h * 64 + nt * 8 + 2 * cq;
                *(float2*)&sY[r0 * YSTRIDE + c]       = make_float2(acc[nt][0], acc[nt][1]);
                *(float2*)&sY[(r0 + 8) * YSTRIDE + c] = make_float2(acc[nt][2], acc[nt][3]);
            }
        }
        __syncthreads();

        // ---- single epilogue: warp w -> rows w*8..w*8+7; Pself run cached ----
#pragma unroll 2
        for (int i = 0; i < 8; i++) {
            int row = wid * 8 + i;
            int e = e0 + row;
            if (e >= E) continue;
            int s = sS[row], n = sN[row];
            if (s != sPrev) {
                ps = ((const float4*)(g_Pself + (size_t)s * 128))[lane];
                sPrev = s;
            }
            float4 a4 = *(const float4*)&sY[row * YSTRIDE + lane * 4];
            float4 pn = ((const float4*)(g_Pnbr + (size_t)n * 128))[lane];
            float y0 = a4.x + ps.x + pn.x;
            float y1 = a4.y + ps.y + pn.y;
            float y2 = a4.z + ps.z + pn.z;
            float y3 = a4.w + ps.w + pn.w;
            st.x += y0; st.y += y1; st.z += y2; st.w += y3;
            sq.x += y0 * y0; sq.y += y1 * y1; sq.z += y2 * y2; sq.w += y3 * y3;
            __half2 p01 = __floats2half2_rn(y0, y1);
            __half2 p23 = __floats2half2_rn(y2, y3);
            uint2 u;
            u.x = *(unsigned*)&p01;
            u.y = *(unsigned*)&p23;
            __stcs((uint2*)(g_yh + (size_t)e * 128 + lane * 4), u);
        }
    }

    // ---- BN1 stats: cross-warp reduce in smem, one atomicAdd per col per CTA ----
    __syncthreads();
    *(float4*)&sY[wid * 128 + lane * 4] = st;
    *(float4*)&sY[1024 + wid * 128 + lane * 4] = sq;
    __syncthreads();
    if (tid < 128) {
        float a = 0.f, b = 0.f;
#pragma unroll
        for (int w = 0; w < 8; w++) {
            a += sY[w * 128 + tid];
            b += sY[1024 + w * 128 + tid];
        }
        atomicAdd(&g_bn1s[tid], a);
        atomicAdd(&g_bn1q[tid], b);
    }
}

// ---------------- k_atom: BN1 fold + message + segment sum + BN2 stats ----------
__global__ __launch_bounds__(256) void k_atom(const float* __restrict__ gamma1,
                                              const float* __restrict__ beta1,
                                              int N, int E) {
    __shared__ float sv[8 * 64], sv2[8 * 64];
    int wid = threadIdx.x >> 5;
    int lane = threadIdx.x & 31;
    int a = blockIdx.x * 8 + wid;
    bool active = a < N;

    // fold BN1 per warp
    float inv_n = 1.0f / (float)E;
    float2 a1f, c1f, a1c, c1c;
    {
        float2 s1 = ((const float2*)g_bn1s)[lane];
        float2 q1 = ((const float2*)g_bn1q)[lane];
        float2 gg = ((const float2*)gamma1)[lane];
        float2 bb = ((const float2*)beta1)[lane];
        float m0 = s1.x * inv_n, m1 = s1.y * inv_n;
        a1f.x = gg.x * rsqrtf(q1.x * inv_n - m0 * m0 + BN_EPS);
        a1f.y = gg.y * rsqrtf(q1.y * inv_n - m1 * m1 + BN_EPS);
        c1f.x = bb.x - a1f.x * m0;
        c1f.y = bb.y - a1f.y * m1;
        float2 s2 = ((const float2*)g_bn1s)[32 + lane];
        float2 q2 = ((const float2*)g_bn1q)[32 + lane];
        float2 g2 = ((const float2*)gamma1)[32 + lane];
        float2 b2 = ((const float2*)beta1)[32 + lane];
        float m2 = s2.x * inv_n, m3 = s2.y * inv_n;
        a1c.x = g2.x * rsqrtf(q2.x * inv_n - m2 * m2 + BN_EPS);
        a1c.y = g2.y * rsqrtf(q2.y * inv_n - m3 * m3 + BN_EPS);
        c1c.x = b2.x - a1c.x * m2;
        c1c.y = b2.y - a1c.y * m3;
    }

    float sx = 0.f, sy = 0.f;
    if (active) {
        int eb = g_start[a], ee = g_start[a + 1];
        int e = eb;
        for (; e + 4 <= ee; e += 4) {
            float2 F[4], G[4];
#pragma unroll
            for (int q = 0; q < 4; q++) {
                const __half2* y = (const __half2*)(g_yh + (size_t)(e + q) * 128);
                F[q] = __half22float2(__ldcs(&y[lane]));
                G[q] = __half22float2(__ldcs(&y[32 + lane]));
            }
#pragma unroll
            for (int q = 0; q < 4; q++) {
                sx += sigmoid_f(fmaf(a1f.x, F[q].x, c1f.x)) * softplus_f(fmaf(a1c.x, G[q].x, c1c.x));
                sy += sigmoid_f(fmaf(a1f.y, F[q].y, c1f.y)) * softplus_f(fmaf(a1c.y, G[q].y, c1c.y));
            }
        }
        for (; e < ee; e++) {
            const __half2* y = (const __half2*)(g_yh + (size_t)e * 128);
            float2 F0 = __half22float2(__ldcs(&y[lane]));
            float2 G0 = __half22float2(__ldcs(&y[32 + lane]));
            sx += sigmoid_f(fmaf(a1f.x, F0.x, c1f.x)) * softplus_f(fmaf(a1c.x, G0.x, c1c.x));
            sy += sigmoid_f(fmaf(a1f.y, F0.y, c1f.y)) * softplus_f(fmaf(a1c.y, G0.y, c1c.y));
        }
        ((float2*)g_ns)[(size_t)a * 32 + lane] = make_float2(sx, sy);
    }

    // BN2 stats: block reduce over 8 atoms, 128 atomics per block
    ((float2*)sv)[wid * 32 + lane]  = make_float2(sx, sy);
    ((float2*)sv2)[wid * 32 + lane] = make_float2(sx * sx, sy * sy);
    __syncthreads();
    if (threadIdx.x < 64) {
        int f = threadIdx.x;
        float s = 0.f, q = 0.f;
#pragma unroll
        for (int w = 0; w < 8; w++) {
            s += sv[w * 64 + f];
            q += sv2[w * 64 + f];
        }
        atomicAdd(&g_bn2s[f], s);
        atomicAdd(&g_bn2q[f], q);
    }
}

// ---------------- fused final ----------------
__global__ void k_final(const float* __restrict__ atom,
                        const float* __restrict__ gamma2,
                        const float* __restrict__ beta2,
                        float* __restrict__ out, int N) {
    int i = blockIdx.x * blockDim.x + threadIdx.x;
    if (i >= N * 64) return;
    int f = i & 63;
    float inv_n = 1.0f / (float)N;
    float mean = g_bn2s[f] * inv_n;
    float var  = g_bn2q[f] * inv_n - mean * mean;
    float a2 = gamma2[f] * rsqrtf(var + BN_EPS);
    float c2 = beta2[f] - a2 * mean;
    float v = atom[i] + a2 * g_ns[i] + c2;
    out[i] = softplus_f(v);
}

// ---------------- launch ----------------
extern "C" void kernel_launch(void* const* d_in, const int* in_sizes, int n_in,
                              void* d_out, int out_size) {
    const float* atom   = (const float*)d_in[0];
    const float* nbr    = (const float*)d_in[1];
    const int*   sidx   = (const int*)d_in[2];
    const int*   nidx   = (const int*)d_in[3];
    const float* W      = (const float*)d_in[4];
    const float* bias   = (const float*)d_in[5];
    const float* gamma1 = (const float*)d_in[6];
    const float* beta1  = (const float*)d_in[7];
    const float* gamma2 = (const float*)d_in[8];
    const float* beta2  = (const float*)d_in[9];
    float* out = (float*)d_out;

    int N = in_sizes[0] / 64;
    int E = in_sizes[2];
    int ET = (E + 63) / 64;
    int MT = (N + 63) / 64;

    cudaFuncSetAttribute(k_edge_mma, cudaFuncAttributeMaxDynamicSharedMemorySize, ESMEM);
    cudaFuncSetAttribute(k_proj_mma, cudaFuncAttributeMaxDynamicSharedMemorySize, PSMEM);

    k_init<<<(N + 256) / 256, 256>>>(N, E);
    {
        dim3 grid(148, 2);
        k_proj_mma<<<grid, 256, PSMEM>>>(atom, W, bias, N, MT);
    }
    k_edge_mma<<<592, 256, ESMEM>>>(nbr, sidx, nidx, W, E, ET);
    k_atom<<<(N + 7) / 8, 256>>>(gamma1, beta1, N, E);
    k_final<<<(N * 64 + 255) / 256, 256>>>(atom, gamma2, beta2, out, N);
}